// round 1
// baseline (speedup 1.0000x reference)
#include <cuda_runtime.h>

#define N_PTS 8192
#define D     256
#define TILE  128
#define KC    64
#define KPAD  4          // KC+4 = 68-float row stride: 16B-aligned float4 stores, 2-way LDS conflict on B (acceptable)

// Scratch (allocation-free rule: __device__ globals)
__device__ float    g_sq1[N_PTS];
__device__ float    g_sq2[N_PTS];
__device__ unsigned g_min1[N_PTS];   // float bits of running min d^2 (>=0, so uint order == float order)
__device__ unsigned g_min2[N_PTS];

// ---------------------------------------------------------------------------
// Kernel 1: squared norms of every row of both sets + init the min arrays.
// One warp per row; 16384 warps total.
// ---------------------------------------------------------------------------
__global__ void norms_init_kernel(const float* __restrict__ s1,
                                  const float* __restrict__ s2) {
    int gw   = (blockIdx.x * blockDim.x + threadIdx.x) >> 5;
    int lane = threadIdx.x & 31;
    const float* src = (gw < N_PTS) ? s1 : s2;
    int row = gw & (N_PTS - 1);
    const float4* p = reinterpret_cast<const float4*>(src + (size_t)row * D);
    float s = 0.f;
#pragma unroll
    for (int i = 0; i < 2; ++i) {               // 64 float4 per row / 32 lanes
        float4 v = p[lane + i * 32];
        s += v.x * v.x + v.y * v.y + v.z * v.z + v.w * v.w;
    }
#pragma unroll
    for (int o = 16; o; o >>= 1) s += __shfl_xor_sync(0xffffffffu, s, o);
    if (lane == 0) {
        if (gw < N_PTS) { g_sq1[row] = s; g_min1[row] = 0x7f7fffffu; }
        else            { g_sq2[row] = s; g_min2[row] = 0x7f7fffffu; }
    }
}

// ---------------------------------------------------------------------------
// Kernel 2: fused Gram-tile + min reduction.
// 128x128 output tile per CTA, 256 threads, 8x8 register block per thread.
// Thread (ty,tx) owns rows {ty + 16i}, cols {tx + 16j} (strided fragments ->
// conflict-free-ish LDS with the 68-float smem row stride).
// ---------------------------------------------------------------------------
__global__ void __launch_bounds__(256, 2)
dist_min_kernel(const float* __restrict__ s1, const float* __restrict__ s2) {
    __shared__ float As[TILE][KC + KPAD];
    __shared__ float Bs[TILE][KC + KPAD];
    __shared__ unsigned cmin_s[TILE];

    const int tid = threadIdx.x;
    const int tx  = tid & 15;
    const int ty  = tid >> 4;
    const int rowBase = blockIdx.y * TILE;
    const int colBase = blockIdx.x * TILE;

    float acc[8][8];
#pragma unroll
    for (int i = 0; i < 8; ++i)
#pragma unroll
        for (int j = 0; j < 8; ++j) acc[i][j] = 0.f;

    for (int kc = 0; kc < D; kc += KC) {
        // Stage 128x64 chunks of both operands (coalesced float4 global loads).
#pragma unroll
        for (int it = 0; it < 8; ++it) {
            int s  = tid + it * 256;             // 2048 float4 slots
            int r  = s >> 4;
            int kq = (s & 15) << 2;
            float4 va = *reinterpret_cast<const float4*>(
                s1 + (size_t)(rowBase + r) * D + kc + kq);
            float4 vb = *reinterpret_cast<const float4*>(
                s2 + (size_t)(colBase + r) * D + kc + kq);
            *reinterpret_cast<float4*>(&As[r][kq]) = va;
            *reinterpret_cast<float4*>(&Bs[r][kq]) = vb;
        }
        __syncthreads();

#pragma unroll 8
        for (int k = 0; k < KC; ++k) {
            float a[8], b[8];
#pragma unroll
            for (int i = 0; i < 8; ++i) a[i] = As[ty + (i << 4)][k];
#pragma unroll
            for (int j = 0; j < 8; ++j) b[j] = Bs[tx + (j << 4)][k];
#pragma unroll
            for (int i = 0; i < 8; ++i)
#pragma unroll
                for (int j = 0; j < 8; ++j)
                    acc[i][j] = fmaf(a[i], b[j], acc[i][j]);
        }
        __syncthreads();
    }

    // ---- Epilogue: d^2 = sq1 + sq2 - 2*gram, clamp, fused min reductions ----
    if (tid < TILE) cmin_s[tid] = 0x7f7fffffu;

    float sqa[8], sqb[8];
#pragma unroll
    for (int i = 0; i < 8; ++i) sqa[i] = g_sq1[rowBase + ty + (i << 4)];
#pragma unroll
    for (int j = 0; j < 8; ++j) sqb[j] = g_sq2[colBase + tx + (j << 4)];
    __syncthreads();

    float cm[8];
#pragma unroll
    for (int j = 0; j < 8; ++j) cm[j] = 3.4028235e38f;

#pragma unroll
    for (int i = 0; i < 8; ++i) {
        float rmin = 3.4028235e38f;
#pragma unroll
        for (int j = 0; j < 8; ++j) {
            float d2 = fmaxf(fmaf(-2.f, acc[i][j], sqa[i] + sqb[j]), 0.f);
            rmin  = fminf(rmin, d2);
            cm[j] = fminf(cm[j], d2);
        }
        // Row min: reduce across the 16 threads (same ty) = one half-warp.
#pragma unroll
        for (int o = 8; o; o >>= 1)
            rmin = fminf(rmin, __shfl_xor_sync(0xffffffffu, rmin, o));
        if (tx == 0)
            atomicMin(&g_min1[rowBase + ty + (i << 4)], __float_as_uint(rmin));
    }

    // Col min: smem atomic combine across the 16 ty-threads per column.
#pragma unroll
    for (int j = 0; j < 8; ++j)
        atomicMin(&cmin_s[tx + (j << 4)], __float_as_uint(cm[j]));
    __syncthreads();
    if (tid < TILE)
        atomicMin(&g_min2[colBase + tid], cmin_s[tid]);
}

// ---------------------------------------------------------------------------
// Kernel 3: mean(sqrt(min1)) + mean(sqrt(min2)) -> scalar.
// ---------------------------------------------------------------------------
__global__ void finalize_kernel(float* __restrict__ out) {
    __shared__ float red[32];
    int tid = threadIdx.x;
    float s = 0.f;
    for (int i = tid; i < N_PTS; i += 1024)
        s += sqrtf(__uint_as_float(g_min1[i])) + sqrtf(__uint_as_float(g_min2[i]));
#pragma unroll
    for (int o = 16; o; o >>= 1) s += __shfl_xor_sync(0xffffffffu, s, o);
    if ((tid & 31) == 0) red[tid >> 5] = s;
    __syncthreads();
    if (tid < 32) {
        float v = (tid < 32) ? red[tid] : 0.f;
#pragma unroll
        for (int o = 16; o; o >>= 1) v += __shfl_xor_sync(0xffffffffu, v, o);
        if (tid == 0) out[0] = v / (float)N_PTS;
    }
}

// ---------------------------------------------------------------------------
extern "C" void kernel_launch(void* const* d_in, const int* in_sizes, int n_in,
                              void* d_out, int out_size) {
    const float* s1 = (const float*)d_in[0];
    const float* s2 = (const float*)d_in[1];

    // norms + init: 16384 warps / 8 warps per block
    norms_init_kernel<<<2 * N_PTS / 8, 256>>>(s1, s2);

    dim3 grid(N_PTS / TILE, N_PTS / TILE);
    dist_min_kernel<<<grid, 256>>>(s1, s2);

    finalize_kernel<<<1, 1024>>>((float*)d_out);
}

// round 4
// speedup vs baseline: 6.2410x; 6.2410x over previous
#include <cuda_runtime.h>
#include <cuda_bf16.h>
#include <cstdint>

#define NP   8192
#define DIM  256
#define KC   32
#define NKC  (DIM / KC)      // 8 K-chunks
#define PIT  40              // smem row pitch in bf16 (32 data + 8 pad) -> 80B, 16B aligned

// ---------------- scratch (allocation-free rule) ----------------
__device__ float          g_sq1[NP];
__device__ float          g_sq2[NP];
__device__ unsigned       g_min1[NP];
__device__ unsigned       g_min2[NP];
__device__ __nv_bfloat16  g_b1[NP * DIM];
__device__ __nv_bfloat16  g_b2[NP * DIM];

__device__ __forceinline__ uint32_t s2u(const void* p) {
    uint32_t a;
    asm("{ .reg .u64 t; cvta.to.shared.u64 t, %1; cvt.u32.u64 %0, t; }"
        : "=r"(a) : "l"(p));
    return a;
}
__device__ __forceinline__ void cp16(uint32_t dst, const void* src) {
    asm volatile("cp.async.cg.shared.global [%0], [%1], 16;"
                 :: "r"(dst), "l"(__cvta_generic_to_global(src)) : "memory");
}
__device__ __forceinline__ void ldm_x4(uint32_t& r0, uint32_t& r1,
                                       uint32_t& r2, uint32_t& r3, uint32_t a) {
    asm volatile("ldmatrix.sync.aligned.m8n8.x4.shared.b16 {%0,%1,%2,%3}, [%4];"
                 : "=r"(r0), "=r"(r1), "=r"(r2), "=r"(r3) : "r"(a));
}
__device__ __forceinline__ void mma16816(float& c0, float& c1, float& c2, float& c3,
                                         uint32_t a0, uint32_t a1, uint32_t a2, uint32_t a3,
                                         uint32_t b0, uint32_t b1) {
    asm volatile("mma.sync.aligned.m16n8k16.row.col.f32.bf16.bf16.f32 "
                 "{%0,%1,%2,%3}, {%4,%5,%6,%7}, {%8,%9}, {%0,%1,%2,%3};"
                 : "+f"(c0), "+f"(c1), "+f"(c2), "+f"(c3)
                 : "r"(a0), "r"(a1), "r"(a2), "r"(a3), "r"(b0), "r"(b1));
}

// ---------------------------------------------------------------------------
// Kernel 1: fp32 -> bf16 conversion + squared norms + min init. 1 warp / row.
// ---------------------------------------------------------------------------
__global__ void prep_kernel(const float* __restrict__ s1,
                            const float* __restrict__ s2) {
    int gw   = (blockIdx.x * blockDim.x + threadIdx.x) >> 5;
    int lane = threadIdx.x & 31;
    bool first = gw < NP;
    int row = gw & (NP - 1);
    const float4* p = reinterpret_cast<const float4*>(
        (first ? s1 : s2) + (size_t)row * DIM);
    __nv_bfloat162* dst = reinterpret_cast<__nv_bfloat162*>(
        (first ? g_b1 : g_b2) + (size_t)row * DIM);
    float s = 0.f;
#pragma unroll
    for (int i = 0; i < 2; ++i) {
        float4 v = p[lane + i * 32];
        s += v.x * v.x + v.y * v.y + v.z * v.z + v.w * v.w;
        dst[(lane + i * 32) * 2]     = __float22bfloat162_rn(make_float2(v.x, v.y));
        dst[(lane + i * 32) * 2 + 1] = __float22bfloat162_rn(make_float2(v.z, v.w));
    }
#pragma unroll
    for (int o = 16; o; o >>= 1) s += __shfl_xor_sync(0xffffffffu, s, o);
    if (lane == 0) {
        if (first) { g_sq1[row] = s; g_min1[row] = 0x7f7fffffu; }
        else       { g_sq2[row] = s; g_min2[row] = 0x7f7fffffu; }
    }
}

// ---------------------------------------------------------------------------
// Kernel 2: bf16 mma.sync Gram tile (128x128, K=256) + fused min epilogue.
// 8 warps: warp_m = wid&3 (32 rows), warp_n = wid>>2 (64 cols).
// ---------------------------------------------------------------------------
__global__ void __launch_bounds__(256, 2)
dist_min_mma_kernel() {
    __shared__ __nv_bfloat16 As[2][128 * PIT];
    __shared__ __nv_bfloat16 Bs[2][128 * PIT];
    __shared__ float sqa_s[128];
    __shared__ float sqb_s[128];

    const int tid  = threadIdx.x;
    const int lane = tid & 31;
    const int wid  = tid >> 5;
    const int wm   = wid & 3;          // 0..3 -> 32-row slice
    const int wn   = wid >> 2;         // 0..1 -> 64-col slice
    const int rowBase = blockIdx.y * 128;
    const int colBase = blockIdx.x * 128;

    if (tid < 128) {
        sqa_s[tid] = g_sq1[rowBase + tid];
        sqb_s[tid] = g_sq2[colBase + tid];
    }

    // ---- cp.async chunk loader: 128 rows x 64B per operand = 512 x 16B ----
    auto load_chunk = [&](int c, int s) {
#pragma unroll
        for (int it = 0; it < 2; ++it) {
            int idx = tid + it * 256;   // 0..511
            int r = idx >> 2;           // 0..127
            int q = idx & 3;            // 0..3 : 16B quarter of the 64B row
            cp16(s2u(&As[s][r * PIT + q * 8]),
                 g_b1 + (size_t)(rowBase + r) * DIM + c * KC + q * 8);
            cp16(s2u(&Bs[s][r * PIT + q * 8]),
                 g_b2 + (size_t)(colBase + r) * DIM + c * KC + q * 8);
        }
        asm volatile("cp.async.commit_group;" ::: "memory");
    };

    float acc[2][8][4];
#pragma unroll
    for (int i = 0; i < 2; ++i)
#pragma unroll
        for (int j = 0; j < 8; ++j)
#pragma unroll
            for (int q = 0; q < 4; ++q) acc[i][j][q] = 0.f;

    load_chunk(0, 0);

    // ldmatrix base addressing (within a stage)
    const int a_row = wm * 32 + (lane & 15);                      // + mt*16
    const int a_kof = (lane >> 4) << 3;                           // k half
    const int b_row = wn * 64 + (lane & 7) + ((lane >> 4) << 3);  // + np*16
    const int b_kof = ((lane >> 3) & 1) << 3;                     // k half

    for (int c = 0; c < NKC; ++c) {
        if (c + 1 < NKC) {
            load_chunk(c + 1, (c + 1) & 1);
            asm volatile("cp.async.wait_group 1;" ::: "memory");
        } else {
            asm volatile("cp.async.wait_group 0;" ::: "memory");
        }
        __syncthreads();

        const __nv_bfloat16* a_st = As[c & 1];
        const __nv_bfloat16* b_st = Bs[c & 1];
#pragma unroll
        for (int ks = 0; ks < 2; ++ks) {
            uint32_t a[2][4], b[4][4];
#pragma unroll
            for (int mt = 0; mt < 2; ++mt)
                ldm_x4(a[mt][0], a[mt][1], a[mt][2], a[mt][3],
                       s2u(a_st + (a_row + mt * 16) * PIT + ks * 16 + a_kof));
#pragma unroll
            for (int np = 0; np < 4; ++np)
                ldm_x4(b[np][0], b[np][1], b[np][2], b[np][3],
                       s2u(b_st + (b_row + np * 16) * PIT + ks * 16 + b_kof));
#pragma unroll
            for (int mt = 0; mt < 2; ++mt)
#pragma unroll
                for (int np = 0; np < 4; ++np) {
                    mma16816(acc[mt][2 * np][0], acc[mt][2 * np][1],
                             acc[mt][2 * np][2], acc[mt][2 * np][3],
                             a[mt][0], a[mt][1], a[mt][2], a[mt][3],
                             b[np][0], b[np][1]);
                    mma16816(acc[mt][2 * np + 1][0], acc[mt][2 * np + 1][1],
                             acc[mt][2 * np + 1][2], acc[mt][2 * np + 1][3],
                             a[mt][0], a[mt][1], a[mt][2], a[mt][3],
                             b[np][2], b[np][3]);
                }
        }
        __syncthreads();
    }

    // ---- Epilogue: d^2 + fused row/col mins, registers + shuffles only ----
    const float FMAX = 3.4028235e38f;
    float rmin[2][2] = {{FMAX, FMAX}, {FMAX, FMAX}};   // [mt][row half]
    float cmin[8][2];                                   // [n8][col parity]
#pragma unroll
    for (int j = 0; j < 8; ++j) cmin[j][0] = cmin[j][1] = FMAX;

#pragma unroll
    for (int mt = 0; mt < 2; ++mt) {
        float sqa0 = sqa_s[wm * 32 + mt * 16 + (lane >> 2)];
        float sqa1 = sqa_s[wm * 32 + mt * 16 + (lane >> 2) + 8];
#pragma unroll
        for (int n8 = 0; n8 < 8; ++n8) {
            float sqb0 = sqb_s[wn * 64 + n8 * 8 + 2 * (lane & 3)];
            float sqb1 = sqb_s[wn * 64 + n8 * 8 + 2 * (lane & 3) + 1];
            float d00 = fmaxf(fmaf(-2.f, acc[mt][n8][0], sqa0 + sqb0), 0.f);
            float d01 = fmaxf(fmaf(-2.f, acc[mt][n8][1], sqa0 + sqb1), 0.f);
            float d10 = fmaxf(fmaf(-2.f, acc[mt][n8][2], sqa1 + sqb0), 0.f);
            float d11 = fmaxf(fmaf(-2.f, acc[mt][n8][3], sqa1 + sqb1), 0.f);
            rmin[mt][0] = fminf(rmin[mt][0], fminf(d00, d01));
            rmin[mt][1] = fminf(rmin[mt][1], fminf(d10, d11));
            cmin[n8][0] = fminf(cmin[n8][0], fminf(d00, d10));
            cmin[n8][1] = fminf(cmin[n8][1], fminf(d01, d11));
        }
    }

    // Row mins: reduce across the quad (threads sharing a row), then atomic.
#pragma unroll
    for (int mt = 0; mt < 2; ++mt)
#pragma unroll
        for (int h = 0; h < 2; ++h) {
            float v = rmin[mt][h];
            v = fminf(v, __shfl_xor_sync(0xffffffffu, v, 1));
            v = fminf(v, __shfl_xor_sync(0xffffffffu, v, 2));
            if ((lane & 3) == 0)
                atomicMin(&g_min1[rowBase + wm * 32 + mt * 16 + h * 8 + (lane >> 2)],
                          __float_as_uint(v));
        }

    // Col mins: reduce across row-groups (xor 4,8,16), then atomic.
#pragma unroll
    for (int n8 = 0; n8 < 8; ++n8)
#pragma unroll
        for (int q = 0; q < 2; ++q) {
            float v = cmin[n8][q];
            v = fminf(v, __shfl_xor_sync(0xffffffffu, v, 4));
            v = fminf(v, __shfl_xor_sync(0xffffffffu, v, 8));
            v = fminf(v, __shfl_xor_sync(0xffffffffu, v, 16));
            if (lane < 4)
                atomicMin(&g_min2[colBase + wn * 64 + n8 * 8 + 2 * lane + q],
                          __float_as_uint(v));
        }
}

// ---------------------------------------------------------------------------
// Kernel 3: mean(sqrt(min1)) + mean(sqrt(min2))
// ---------------------------------------------------------------------------
__global__ void finalize_kernel(float* __restrict__ out) {
    __shared__ float red[32];
    int tid = threadIdx.x;
    float s = 0.f;
    for (int i = tid; i < NP; i += 1024)
        s += sqrtf(__uint_as_float(g_min1[i])) + sqrtf(__uint_as_float(g_min2[i]));
#pragma unroll
    for (int o = 16; o; o >>= 1) s += __shfl_xor_sync(0xffffffffu, s, o);
    if ((tid & 31) == 0) red[tid >> 5] = s;
    __syncthreads();
    if (tid < 32) {
        float v = red[tid];
#pragma unroll
        for (int o = 16; o; o >>= 1) v += __shfl_xor_sync(0xffffffffu, v, o);
        if (tid == 0) out[0] = v / (float)NP;
    }
}

// ---------------------------------------------------------------------------
extern "C" void kernel_launch(void* const* d_in, const int* in_sizes, int n_in,
                              void* d_out, int out_size) {
    const float* s1 = (const float*)d_in[0];
    const float* s2 = (const float*)d_in[1];

    prep_kernel<<<2 * NP / 8, 256>>>(s1, s2);

    dim3 grid(NP / 128, NP / 128);
    dist_min_mma_kernel<<<grid, 256>>>();

    finalize_kernel<<<1, 1024>>>((float*)d_out);
}

// round 5
// speedup vs baseline: 6.6030x; 1.0580x over previous
#include <cuda_runtime.h>
#include <cuda_bf16.h>
#include <cstdint>

#define NP    8192
#define DIM   256
#define KC    64
#define NKC   (DIM / KC)         // 4 K-chunks
#define TM    128                // CTA rows
#define TN    256                // CTA cols
#define PITB  144                // smem row pitch bytes: 64 bf16 data + 8 pad = 72*2

// smem byte offsets (dynamic)
#define OFF_A(s)  ((s) * 18432)                 // 128 rows * 144B
#define OFF_B(s)  (36864 + (s) * 36864)         // 256 rows * 144B
#define OFF_SQA   110592
#define OFF_SQB   111104
#define SMEM_TOT  112128

// ---------------- scratch (allocation-free rule) ----------------
__device__ float          g_sq1[NP];
__device__ float          g_sq2[NP];
__device__ unsigned       g_min1[NP];
__device__ unsigned       g_min2[NP];
__device__ __nv_bfloat16  g_b1[NP * DIM];
__device__ __nv_bfloat16  g_b2[NP * DIM];

__device__ __forceinline__ uint32_t s2u(const void* p) {
    uint32_t a;
    asm("{ .reg .u64 t; cvta.to.shared.u64 t, %1; cvt.u32.u64 %0, t; }"
        : "=r"(a) : "l"(p));
    return a;
}
__device__ __forceinline__ void cp16(uint32_t dst, const void* src) {
    asm volatile("cp.async.cg.shared.global [%0], [%1], 16;"
                 :: "r"(dst), "l"(__cvta_generic_to_global(src)) : "memory");
}
__device__ __forceinline__ void ldm_x4(uint32_t& r0, uint32_t& r1,
                                       uint32_t& r2, uint32_t& r3, uint32_t a) {
    asm volatile("ldmatrix.sync.aligned.m8n8.x4.shared.b16 {%0,%1,%2,%3}, [%4];"
                 : "=r"(r0), "=r"(r1), "=r"(r2), "=r"(r3) : "r"(a));
}
__device__ __forceinline__ void mma16816(float& c0, float& c1, float& c2, float& c3,
                                         uint32_t a0, uint32_t a1, uint32_t a2, uint32_t a3,
                                         uint32_t b0, uint32_t b1) {
    asm volatile("mma.sync.aligned.m16n8k16.row.col.f32.bf16.bf16.f32 "
                 "{%0,%1,%2,%3}, {%4,%5,%6,%7}, {%8,%9}, {%0,%1,%2,%3};"
                 : "+f"(c0), "+f"(c1), "+f"(c2), "+f"(c3)
                 : "r"(a0), "r"(a1), "r"(a2), "r"(a3), "r"(b0), "r"(b1));
}

// ---------------------------------------------------------------------------
// Kernel 1: fp32 -> bf16 conversion + squared norms + min init. 1 warp / row.
// ---------------------------------------------------------------------------
__global__ void prep_kernel(const float* __restrict__ s1,
                            const float* __restrict__ s2) {
    int gw   = (blockIdx.x * blockDim.x + threadIdx.x) >> 5;
    int lane = threadIdx.x & 31;
    bool first = gw < NP;
    int row = gw & (NP - 1);
    const float4* p = reinterpret_cast<const float4*>(
        (first ? s1 : s2) + (size_t)row * DIM);
    __nv_bfloat162* dst = reinterpret_cast<__nv_bfloat162*>(
        (first ? g_b1 : g_b2) + (size_t)row * DIM);
    float s = 0.f;
#pragma unroll
    for (int i = 0; i < 2; ++i) {
        float4 v = p[lane + i * 32];
        s += v.x * v.x + v.y * v.y + v.z * v.z + v.w * v.w;
        dst[(lane + i * 32) * 2]     = __float22bfloat162_rn(make_float2(v.x, v.y));
        dst[(lane + i * 32) * 2 + 1] = __float22bfloat162_rn(make_float2(v.z, v.w));
    }
#pragma unroll
    for (int o = 16; o; o >>= 1) s += __shfl_xor_sync(0xffffffffu, s, o);
    if (lane == 0) {
        if (first) { g_sq1[row] = s; g_min1[row] = 0x7f7fffffu; }
        else       { g_sq2[row] = s; g_min2[row] = 0x7f7fffffu; }
    }
}

// ---------------------------------------------------------------------------
// Kernel 2: 128x256 CTA tile, 8 warps (2x4), 64x64 warp tile, KC=64, 2-stage.
// ---------------------------------------------------------------------------
__global__ void __launch_bounds__(256, 1)
dist_min_mma_kernel() {
    extern __shared__ char smem[];
    const uint32_t sb = s2u(smem);
    float* sqa_s = reinterpret_cast<float*>(smem + OFF_SQA);
    float* sqb_s = reinterpret_cast<float*>(smem + OFF_SQB);

    const int tid  = threadIdx.x;
    const int lane = tid & 31;
    const int wid  = tid >> 5;
    const int wm   = wid & 1;          // 0..1 -> 64-row slice
    const int wn   = wid >> 1;         // 0..3 -> 64-col slice
    const int rowBase = blockIdx.y * TM;
    const int colBase = blockIdx.x * TN;

    if (tid < 128) sqa_s[tid] = g_sq1[rowBase + tid];
    sqb_s[tid] = g_sq2[colBase + tid];

    // ---- chunk loader: A 128 rows + B 256 rows, 128B/row -> 3072 x 16B ----
    auto load_chunk = [&](int c, int s) {
        const __nv_bfloat16* ga = g_b1 + (size_t)rowBase * DIM + c * KC;
        const __nv_bfloat16* gb = g_b2 + (size_t)colBase * DIM + c * KC;
        uint32_t da = sb + OFF_A(s);
        uint32_t db = sb + OFF_B(s);
#pragma unroll
        for (int it = 0; it < 4; ++it) {
            int idx = tid + it * 256;          // 0..1023
            int r = idx >> 3, q = idx & 7;
            cp16(da + r * PITB + q * 16, ga + (size_t)r * DIM + q * 8);
        }
#pragma unroll
        for (int it = 0; it < 8; ++it) {
            int idx = tid + it * 256;          // 0..2047
            int r = idx >> 3, q = idx & 7;
            cp16(db + r * PITB + q * 16, gb + (size_t)r * DIM + q * 8);
        }
        asm volatile("cp.async.commit_group;" ::: "memory");
    };

    float acc[4][8][4];
#pragma unroll
    for (int i = 0; i < 4; ++i)
#pragma unroll
        for (int j = 0; j < 8; ++j)
#pragma unroll
            for (int q = 0; q < 4; ++q) acc[i][j][q] = 0.f;

    load_chunk(0, 0);

    // ldmatrix addressing (bytes)
    const uint32_t a_base = (uint32_t)((wm * 64 + (lane & 15)) * PITB
                                       + ((lane >> 4) << 4));
    const uint32_t b_base = (uint32_t)((wn * 64 + (lane & 7) + ((lane >> 4) << 3)) * PITB
                                       + (((lane >> 3) & 1) << 4));

    for (int c = 0; c < NKC; ++c) {
        if (c + 1 < NKC) {
            load_chunk(c + 1, (c + 1) & 1);
            asm volatile("cp.async.wait_group 1;" ::: "memory");
        } else {
            asm volatile("cp.async.wait_group 0;" ::: "memory");
        }
        __syncthreads();

        const uint32_t sa = sb + OFF_A(c & 1) + a_base;
        const uint32_t sbb = sb + OFF_B(c & 1) + b_base;
#pragma unroll
        for (int ks = 0; ks < 4; ++ks) {
            uint32_t a[4][4], b[4][4];
#pragma unroll
            for (int mt = 0; mt < 4; ++mt)
                ldm_x4(a[mt][0], a[mt][1], a[mt][2], a[mt][3],
                       sa + mt * 16 * PITB + ks * 32);
#pragma unroll
            for (int np = 0; np < 4; ++np)
                ldm_x4(b[np][0], b[np][1], b[np][2], b[np][3],
                       sbb + np * 16 * PITB + ks * 32);
#pragma unroll
            for (int mt = 0; mt < 4; ++mt)
#pragma unroll
                for (int np = 0; np < 4; ++np) {
                    mma16816(acc[mt][2 * np][0], acc[mt][2 * np][1],
                             acc[mt][2 * np][2], acc[mt][2 * np][3],
                             a[mt][0], a[mt][1], a[mt][2], a[mt][3],
                             b[np][0], b[np][1]);
                    mma16816(acc[mt][2 * np + 1][0], acc[mt][2 * np + 1][1],
                             acc[mt][2 * np + 1][2], acc[mt][2 * np + 1][3],
                             a[mt][0], a[mt][1], a[mt][2], a[mt][3],
                             b[np][2], b[np][3]);
                }
        }
        __syncthreads();
    }

    // ---- Epilogue: d^2 + fused row/col mins, registers + shuffles only ----
    const float FMAX = 3.4028235e38f;
    float rmin[4][2];
#pragma unroll
    for (int i = 0; i < 4; ++i) rmin[i][0] = rmin[i][1] = FMAX;
    float cmin[8][2];
#pragma unroll
    for (int j = 0; j < 8; ++j) cmin[j][0] = cmin[j][1] = FMAX;

#pragma unroll
    for (int mt = 0; mt < 4; ++mt) {
        float sqa0 = sqa_s[wm * 64 + mt * 16 + (lane >> 2)];
        float sqa1 = sqa_s[wm * 64 + mt * 16 + (lane >> 2) + 8];
#pragma unroll
        for (int n8 = 0; n8 < 8; ++n8) {
            float sqb0 = sqb_s[wn * 64 + n8 * 8 + 2 * (lane & 3)];
            float sqb1 = sqb_s[wn * 64 + n8 * 8 + 2 * (lane & 3) + 1];
            float d00 = fmaxf(fmaf(-2.f, acc[mt][n8][0], sqa0 + sqb0), 0.f);
            float d01 = fmaxf(fmaf(-2.f, acc[mt][n8][1], sqa0 + sqb1), 0.f);
            float d10 = fmaxf(fmaf(-2.f, acc[mt][n8][2], sqa1 + sqb0), 0.f);
            float d11 = fmaxf(fmaf(-2.f, acc[mt][n8][3], sqa1 + sqb1), 0.f);
            rmin[mt][0] = fminf(rmin[mt][0], fminf(d00, d01));
            rmin[mt][1] = fminf(rmin[mt][1], fminf(d10, d11));
            cmin[n8][0] = fminf(cmin[n8][0], fminf(d00, d10));
            cmin[n8][1] = fminf(cmin[n8][1], fminf(d01, d11));
        }
    }

    // Row mins: reduce across quad (lane xor 1,2), one atomic per row per warp.
#pragma unroll
    for (int mt = 0; mt < 4; ++mt)
#pragma unroll
        for (int h = 0; h < 2; ++h) {
            float v = rmin[mt][h];
            v = fminf(v, __shfl_xor_sync(0xffffffffu, v, 1));
            v = fminf(v, __shfl_xor_sync(0xffffffffu, v, 2));
            if ((lane & 3) == 0)
                atomicMin(&g_min1[rowBase + wm * 64 + mt * 16 + h * 8 + (lane >> 2)],
                          __float_as_uint(v));
        }

    // Col mins: reduce across row-groups (lane xor 4,8,16), atomic from lane<4.
#pragma unroll
    for (int n8 = 0; n8 < 8; ++n8)
#pragma unroll
        for (int q = 0; q < 2; ++q) {
            float v = cmin[n8][q];
            v = fminf(v, __shfl_xor_sync(0xffffffffu, v, 4));
            v = fminf(v, __shfl_xor_sync(0xffffffffu, v, 8));
            v = fminf(v, __shfl_xor_sync(0xffffffffu, v, 16));
            if (lane < 4)
                atomicMin(&g_min2[colBase + wn * 64 + n8 * 8 + 2 * lane + q],
                          __float_as_uint(v));
        }
}

// ---------------------------------------------------------------------------
// Kernel 3: mean(sqrt(min1)) + mean(sqrt(min2))
// ---------------------------------------------------------------------------
__global__ void finalize_kernel(float* __restrict__ out) {
    __shared__ float red[32];
    int tid = threadIdx.x;
    float s = 0.f;
    for (int i = tid; i < NP; i += 1024)
        s += sqrtf(__uint_as_float(g_min1[i])) + sqrtf(__uint_as_float(g_min2[i]));
#pragma unroll
    for (int o = 16; o; o >>= 1) s += __shfl_xor_sync(0xffffffffu, s, o);
    if ((tid & 31) == 0) red[tid >> 5] = s;
    __syncthreads();
    if (tid < 32) {
        float v = red[tid];
#pragma unroll
        for (int o = 16; o; o >>= 1) v += __shfl_xor_sync(0xffffffffu, v, o);
        if (tid == 0) out[0] = v / (float)NP;
    }
}

// ---------------------------------------------------------------------------
extern "C" void kernel_launch(void* const* d_in, const int* in_sizes, int n_in,
                              void* d_out, int out_size) {
    const float* s1 = (const float*)d_in[0];
    const float* s2 = (const float*)d_in[1];

    static bool attr_set = false;
    if (!attr_set) {
        cudaFuncSetAttribute(dist_min_mma_kernel,
                             cudaFuncAttributeMaxDynamicSharedMemorySize, SMEM_TOT);
        attr_set = true;
    }

    prep_kernel<<<2 * NP / 8, 256>>>(s1, s2);

    dim3 grid(NP / TN, NP / TM);
    dist_min_mma_kernel<<<grid, 256, SMEM_TOT>>>();

    finalize_kernel<<<1, 1024>>>((float*)d_out);
}